// round 1
// baseline (speedup 1.0000x reference)
#include <cuda_runtime.h>
#include <cstdint>

// ---------------------------------------------------------------------------
// HOP interaction layer, factorized:
//   G[j,o,d]  = sum_f feat[j,f] * W[d,o,f]          (kernel 1, GEMM-like)
//   tf[a,c,o] = sum_{p in seg(a)} rhat[p,c] * sum_d sense[p,d] * G[j_p,o,d]
//   out[a,o]  = GN/invariants/mixing(tf) + self(feat[a])   (kernel 2, fused)
// G is stored [atom][o][d] so kernel 2 reads each row as 4x LDG.128, fully
// coalesced across the warp (lane = o).
// ---------------------------------------------------------------------------

#define HARD_CUTOFF 6.5f
#define GN_EPS 1e-5f
#define PI_OVER_13 0.2416609733530618f  // 0.5*pi/6.5

// scratch: G, max 8192 atoms * 512 floats = 16 MB
__device__ float g_G[8192 * 512];

__global__ void k1_precompute_G(const float* __restrict__ feat,
                                const float* __restrict__ W,  // [d][o][f] 16x32x32
                                int n_atoms) {
    extern __shared__ float Ws[];  // transposed [f][d][o] = 32*16*32 floats (64KB)
    for (int i = threadIdx.x; i < 16384; i += blockDim.x) {
        int d = i >> 10;
        int rem = i & 1023;
        int o = rem >> 5;
        int f = rem & 31;
        Ws[f * 512 + d * 32 + o] = W[i];
    }
    __syncthreads();

    const int lane = threadIdx.x & 31;
    const int warp = threadIdx.x >> 5;
    const int warps_per_blk = blockDim.x >> 5;
    const int nwarps = warps_per_blk * gridDim.x;
    const int gw = blockIdx.x * warps_per_blk + warp;

    for (int a0 = gw * 4; a0 < n_atoms; a0 += nwarps * 4) {
        float fv[4];
#pragma unroll
        for (int k = 0; k < 4; k++)
            fv[k] = (a0 + k < n_atoms) ? feat[(a0 + k) * 32 + lane] : 0.0f;

        float acc[4][16];
#pragma unroll
        for (int k = 0; k < 4; k++)
#pragma unroll
            for (int d = 0; d < 16; d++) acc[k][d] = 0.0f;

#pragma unroll
        for (int f = 0; f < 32; f++) {
            float b0 = __shfl_sync(0xffffffffu, fv[0], f);
            float b1 = __shfl_sync(0xffffffffu, fv[1], f);
            float b2 = __shfl_sync(0xffffffffu, fv[2], f);
            float b3 = __shfl_sync(0xffffffffu, fv[3], f);
#pragma unroll
            for (int d = 0; d < 16; d++) {
                float w = Ws[f * 512 + d * 32 + lane];
                acc[0][d] = fmaf(b0, w, acc[0][d]);
                acc[1][d] = fmaf(b1, w, acc[1][d]);
                acc[2][d] = fmaf(b2, w, acc[2][d]);
                acc[3][d] = fmaf(b3, w, acc[3][d]);
            }
        }

#pragma unroll
        for (int k = 0; k < 4; k++) {
            int a = a0 + k;
            if (a < n_atoms) {
                float4* dst = (float4*)(g_G + (size_t)a * 512 + lane * 16);
                dst[0] = make_float4(acc[k][0], acc[k][1], acc[k][2], acc[k][3]);
                dst[1] = make_float4(acc[k][4], acc[k][5], acc[k][6], acc[k][7]);
                dst[2] = make_float4(acc[k][8], acc[k][9], acc[k][10], acc[k][11]);
                dst[3] = make_float4(acc[k][12], acc[k][13], acc[k][14], acc[k][15]);
            }
        }
    }
}

__device__ __forceinline__ int lower_bound_i(const int* __restrict__ arr, int n, int key) {
    int lo = 0, hi = n;
    while (lo < hi) {
        int mid = (lo + hi) >> 1;
        if (__ldg(arr + mid) < key) lo = mid + 1; else hi = mid;
    }
    return lo;
}

__device__ __forceinline__ float warp_sum(float v) {
#pragma unroll
    for (int o = 16; o > 0; o >>= 1) v += __shfl_xor_sync(0xffffffffu, v, o);
    return v;
}

__global__ void k2_main(const float* __restrict__ feat,
                        const float* __restrict__ rhats,   // [P][4]
                        const float* __restrict__ dist,    // [P]
                        const float* __restrict__ selfW,   // [o][f] 32x32
                        const float* __restrict__ selfB,   // [32]
                        const float* __restrict__ Mw,      // [(o*2+g)][oo] 64x32
                        const float* __restrict__ gnw,     // [64]
                        const float* __restrict__ gnb,     // [64]
                        const float* __restrict__ mu,      // [16]
                        const float* __restrict__ sigma,   // [16]
                        const int* __restrict__ pf,        // [P] sorted
                        const int* __restrict__ ps,        // [P]
                        float* __restrict__ out,           // [N][32]
                        int n_atoms, int n_pairs) {
    const int a = blockIdx.x * (blockDim.x >> 5) + (threadIdx.x >> 5);
    if (a >= n_atoms) return;
    const int lane = threadIdx.x & 31;

    const float mu_l = __ldg(mu + (lane & 15));
    const float inv_sg = 1.0f / __ldg(sigma + (lane & 15));

    const int pstart = lower_bound_i(pf, n_pairs, a);
    const int pend = lower_bound_i(pf, n_pairs, a + 1);

    float tf0 = 0.f, tf1 = 0.f, tf2 = 0.f, tf3 = 0.f;

    for (int p = pstart; p < pend; ++p) {
        int j = __ldg(ps + p);
        float d = __ldg(dist + p);
        float invd = 1.0f / d;
        float z = (invd - mu_l) * inv_sg;
        float cc = cosf(PI_OVER_13 * d);
        float cut = (d < HARD_CUTOFF) ? cc * cc : 0.0f;
        float s = __expf(-0.5f * z * z) * cut;  // valid on lanes 0..15

        const float4* Gp = (const float4*)(g_G + (size_t)j * 512 + lane * 16);
        float4 g0 = Gp[0], g1 = Gp[1], g2 = Gp[2], g3 = Gp[3];

        float h = 0.f;
        h = fmaf(__shfl_sync(0xffffffffu, s, 0), g0.x, h);
        h = fmaf(__shfl_sync(0xffffffffu, s, 1), g0.y, h);
        h = fmaf(__shfl_sync(0xffffffffu, s, 2), g0.z, h);
        h = fmaf(__shfl_sync(0xffffffffu, s, 3), g0.w, h);
        h = fmaf(__shfl_sync(0xffffffffu, s, 4), g1.x, h);
        h = fmaf(__shfl_sync(0xffffffffu, s, 5), g1.y, h);
        h = fmaf(__shfl_sync(0xffffffffu, s, 6), g1.z, h);
        h = fmaf(__shfl_sync(0xffffffffu, s, 7), g1.w, h);
        h = fmaf(__shfl_sync(0xffffffffu, s, 8), g2.x, h);
        h = fmaf(__shfl_sync(0xffffffffu, s, 9), g2.y, h);
        h = fmaf(__shfl_sync(0xffffffffu, s, 10), g2.z, h);
        h = fmaf(__shfl_sync(0xffffffffu, s, 11), g2.w, h);
        h = fmaf(__shfl_sync(0xffffffffu, s, 12), g3.x, h);
        h = fmaf(__shfl_sync(0xffffffffu, s, 13), g3.y, h);
        h = fmaf(__shfl_sync(0xffffffffu, s, 14), g3.z, h);
        h = fmaf(__shfl_sync(0xffffffffu, s, 15), g3.w, h);

        float4 r = *(const float4*)(rhats + 4 * p);
        tf0 = fmaf(r.x, h, tf0);
        tf1 = fmaf(r.y, h, tf1);
        tf2 = fmaf(r.z, h, tf2);
        tf3 = fmaf(r.w, h, tf3);
    }

    // invariants: i0 = l=0 part, i1 = |l=1 vector|^2
    float i0 = tf0;
    float i1 = tf1 * tf1 + tf2 * tf2 + tf3 * tf3;

    // GroupNorm per group (population variance, two-pass for stability)
    float m0 = warp_sum(i0) * (1.0f / 32.0f);
    float m1 = warp_sum(i1) * (1.0f / 32.0f);
    float d0 = i0 - m0, d1 = i1 - m1;
    float v0 = warp_sum(d0 * d0) * (1.0f / 32.0f);
    float v1 = warp_sum(d1 * d1) * (1.0f / 32.0f);
    float x0 = d0 * rsqrtf(v0 + GN_EPS) * __ldg(gnw + lane) + __ldg(gnb + lane);
    float x1 = d1 * rsqrtf(v1 + GN_EPS) * __ldg(gnw + 32 + lane) + __ldg(gnb + 32 + lane);

    // mixing: mix[oo=lane] = sum_{o,g} xn[g][o] * Mw[(o*2+g)*32 + oo]
    float mix = 0.f;
#pragma unroll
    for (int o = 0; o < 32; o++) {
        float a0 = __shfl_sync(0xffffffffu, x0, o);
        float a1 = __shfl_sync(0xffffffffu, x1, o);
        mix = fmaf(a0, __ldg(Mw + (o * 2 + 0) * 32 + lane), mix);
        mix = fmaf(a1, __ldg(Mw + (o * 2 + 1) * 32 + lane), mix);
    }

    // self interaction: self[o=lane] = sum_f feat[a][f] * selfW[o][f] + b[o]
    float fv = feat[a * 32 + lane];
    float sp = __ldg(selfB + lane);
#pragma unroll
    for (int f = 0; f < 32; f++) {
        float ff = __shfl_sync(0xffffffffu, fv, f);
        sp = fmaf(ff, __ldg(selfW + lane * 32 + f), sp);
    }

    out[a * 32 + lane] = mix + sp;
}

extern "C" void kernel_launch(void* const* d_in, const int* in_sizes, int n_in,
                              void* d_out, int out_size) {
    const float* in_features = (const float*)d_in[0];
    const float* tensor_rhats = (const float*)d_in[1];
    const float* dist_pairs = (const float*)d_in[2];
    const float* int_weights = (const float*)d_in[3];
    const float* selfint_w = (const float*)d_in[4];
    const float* selfint_b = (const float*)d_in[5];
    const float* mixing_weights = (const float*)d_in[6];
    const float* gn_weight = (const float*)d_in[7];
    const float* gn_bias = (const float*)d_in[8];
    const float* sens_mu = (const float*)d_in[9];
    const float* sens_sigma = (const float*)d_in[10];
    const int* pair_first = (const int*)d_in[11];
    const int* pair_second = (const int*)d_in[12];
    float* out = (float*)d_out;

    int n_atoms = in_sizes[0] / 32;
    int n_pairs = in_sizes[2];

    cudaFuncSetAttribute(k1_precompute_G,
                         cudaFuncAttributeMaxDynamicSharedMemorySize, 65536);

    // kernel 1: G precompute. 250 blocks x 8 warps x 4 atoms = 8000 atoms.
    int k1_blocks = (n_atoms + 31) / 32;
    k1_precompute_G<<<k1_blocks, 256, 65536>>>(in_features, int_weights, n_atoms);

    // kernel 2: fused pair accumulation + invariants + GN + mixing + self.
    int k2_blocks = (n_atoms + 7) / 8;
    k2_main<<<k2_blocks, 256>>>(in_features, tensor_rhats, dist_pairs,
                                selfint_w, selfint_b, mixing_weights,
                                gn_weight, gn_bias, sens_mu, sens_sigma,
                                pair_first, pair_second, out,
                                n_atoms, n_pairs);
}

// round 3
// speedup vs baseline: 1.0625x; 1.0625x over previous
#include <cuda_runtime.h>
#include <cstdint>

// ---------------------------------------------------------------------------
// HOP interaction layer, factorized:
//   k0: seg_start[a] from sorted pair_first (kills per-warp binary search)
//   k1: G[j,o,d] = sum_f feat[j,f] * W[d,o,f]   (packed f32x2 FMA GEMM)
//   k2: tf[a,c,o] = sum_{p in seg(a)} rhat[p,c] * sum_d sense[p,d]*G[j_p,o,d]
//       + invariants + GroupNorm + mixing + self  (fused, software-pipelined)
// ---------------------------------------------------------------------------

#define HARD_CUTOFF 6.5f
#define GN_EPS 1e-5f
#define PI_OVER_13 0.2416609733530618f  // 0.5*pi/6.5

typedef unsigned long long ull;

__device__ float g_G[8192 * 512];      // 16 MB scratch, fits in L2
__device__ int g_seg[8192 + 1];

__device__ __forceinline__ ull pack2(float lo, float hi) {
    ull r;
    asm("mov.b64 %0, {%1, %2};" : "=l"(r) : "f"(lo), "f"(hi));
    return r;
}
__device__ __forceinline__ void unpack2(ull v, float& lo, float& hi) {
    asm("mov.b64 {%0, %1}, %2;" : "=f"(lo), "=f"(hi) : "l"(v));
}
__device__ __forceinline__ ull ffma2(ull a, ull b, ull c) {
    ull d;
    asm("fma.rn.f32x2 %0, %1, %2, %3;" : "=l"(d) : "l"(a), "l"(b), "l"(c));
    return d;
}

// ---- k0: segment starts from sorted pair_first --------------------------
__global__ void k0_seg(const int* __restrict__ pf, int n_pairs, int n_atoms) {
    int p = blockIdx.x * blockDim.x + threadIdx.x;
    if (p > n_pairs) return;
    int cur  = (p < n_pairs) ? pf[p] : n_atoms;
    int prev = (p == 0) ? -1 : pf[p - 1];
    if (cur > n_atoms) cur = n_atoms;
    if (prev > n_atoms) prev = n_atoms;
    for (int a = prev + 1; a <= cur; ++a) g_seg[a] = p;
}

// ---- k1: G precompute, packed fp32x2 ------------------------------------
__global__ void k1_precompute_G(const float* __restrict__ feat,
                                const float* __restrict__ W,  // [d][o][f] 16x32x32
                                int n_atoms) {
    extern __shared__ float Ws[];  // [f][d2][o][e] : f*512 + d2*64 + o*2 + e
    for (int i = threadIdx.x; i < 16384; i += blockDim.x) {
        int d = i >> 10;
        int rem = i & 1023;
        int o = rem >> 5;
        int f = rem & 31;
        Ws[f * 512 + (d >> 1) * 64 + o * 2 + (d & 1)] = W[i];
    }
    __syncthreads();
    const ull* S2 = (const ull*)Ws;  // index: f*256 + q*32 + o  (q = d/2)

    const int lane = threadIdx.x & 31;
    const int warp = threadIdx.x >> 5;
    const int warps_per_blk = blockDim.x >> 5;
    const int nwarps = warps_per_blk * gridDim.x;
    const int gw = blockIdx.x * warps_per_blk + warp;

    for (int a0 = gw * 4; a0 < n_atoms; a0 += nwarps * 4) {
        float fv[4];
#pragma unroll
        for (int k = 0; k < 4; k++)
            fv[k] = (a0 + k < n_atoms) ? feat[(a0 + k) * 32 + lane] : 0.0f;

        ull acc[4][8];
#pragma unroll
        for (int k = 0; k < 4; k++)
#pragma unroll
            for (int q = 0; q < 8; q++) acc[k][q] = pack2(0.f, 0.f);

#pragma unroll
        for (int f = 0; f < 32; f++) {
            ull w[8];
#pragma unroll
            for (int q = 0; q < 8; q++) w[q] = S2[f * 256 + q * 32 + lane];
#pragma unroll
            for (int k = 0; k < 4; k++) {
                float b = __shfl_sync(0xffffffffu, fv[k], f);
                ull b2 = pack2(b, b);
#pragma unroll
                for (int q = 0; q < 8; q++) acc[k][q] = ffma2(b2, w[q], acc[k][q]);
            }
        }

#pragma unroll
        for (int k = 0; k < 4; k++) {
            int a = a0 + k;
            if (a < n_atoms) {
                float4* dst = (float4*)(g_G + (size_t)a * 512 + lane * 16);
#pragma unroll
                for (int v = 0; v < 4; v++) {
                    float x0, x1, x2, x3;
                    unpack2(acc[k][2 * v], x0, x1);
                    unpack2(acc[k][2 * v + 1], x2, x3);
                    dst[v] = make_float4(x0, x1, x2, x3);
                }
            }
        }
    }
}

__device__ __forceinline__ float warp_sum(float v) {
#pragma unroll
    for (int o = 16; o > 0; o >>= 1) v += __shfl_xor_sync(0xffffffffu, v, o);
    return v;
}

// ---- k2: fused pair accumulation + epilogue -----------------------------
__global__ void k2_main(const float* __restrict__ feat,
                        const float* __restrict__ rhats,   // [P][4]
                        const float* __restrict__ dist,    // [P]
                        const float* __restrict__ selfW,   // [o][f] 32x32
                        const float* __restrict__ selfB,   // [32]
                        const float* __restrict__ Mw,      // [(o*2+g)][oo] 64x32
                        const float* __restrict__ gnw,     // [64]
                        const float* __restrict__ gnb,     // [64]
                        const float* __restrict__ mu,      // [16]
                        const float* __restrict__ sigma,   // [16]
                        const int* __restrict__ ps,        // [P]
                        float* __restrict__ out,           // [N][32]
                        int n_atoms, int n_pairs) {
    const int a = blockIdx.x * (blockDim.x >> 5) + (threadIdx.x >> 5);
    if (a >= n_atoms) return;
    const int lane = threadIdx.x & 31;

    const float mu_l = __ldg(mu + (lane & 15));
    const float inv_sg = __fdividef(1.0f, __ldg(sigma + (lane & 15)));

    const int pstart = g_seg[a];
    const int pend = g_seg[a + 1];

    float tf0 = 0.f, tf1 = 0.f, tf2 = 0.f, tf3 = 0.f;

    if (pstart < pend) {
        // prologue prefetch for first pair
        int j = __ldg(ps + pstart);
        float d = __ldg(dist + pstart);
        float4 r = *(const float4*)(rhats + 4 * pstart);
        const float4* Gp = (const float4*)(g_G + (size_t)j * 512 + lane * 16);
        float4 g0 = __ldg(Gp + 0), g1 = __ldg(Gp + 1),
               g2 = __ldg(Gp + 2), g3 = __ldg(Gp + 3);

        for (int p = pstart; p < pend; ++p) {
            // prefetch next iteration (clamped on last iter; redundant L1 hits)
            int pn = (p + 1 < pend) ? p + 1 : p;
            int jn = __ldg(ps + pn);
            float dn = __ldg(dist + pn);
            float4 rn = *(const float4*)(rhats + 4 * pn);
            const float4* Gn = (const float4*)(g_G + (size_t)jn * 512 + lane * 16);
            float4 n0 = __ldg(Gn + 0), n1 = __ldg(Gn + 1),
                   n2 = __ldg(Gn + 2), n3 = __ldg(Gn + 3);

            // sensitivity (valid on lanes 0..15), overlaps the G-load latency
            float invd = __fdividef(1.0f, d);
            float z = (invd - mu_l) * inv_sg;
            float cc = __cosf(PI_OVER_13 * d);
            float cut = (d < HARD_CUTOFF) ? cc * cc : 0.0f;
            float s = __expf(-0.5f * z * z) * cut;

            float hA = 0.f, hB = 0.f, hC = 0.f, hD = 0.f;
            hA = fmaf(__shfl_sync(0xffffffffu, s, 0), g0.x, hA);
            hA = fmaf(__shfl_sync(0xffffffffu, s, 1), g0.y, hA);
            hA = fmaf(__shfl_sync(0xffffffffu, s, 2), g0.z, hA);
            hA = fmaf(__shfl_sync(0xffffffffu, s, 3), g0.w, hA);
            hB = fmaf(__shfl_sync(0xffffffffu, s, 4), g1.x, hB);
            hB = fmaf(__shfl_sync(0xffffffffu, s, 5), g1.y, hB);
            hB = fmaf(__shfl_sync(0xffffffffu, s, 6), g1.z, hB);
            hB = fmaf(__shfl_sync(0xffffffffu, s, 7), g1.w, hB);
            hC = fmaf(__shfl_sync(0xffffffffu, s, 8), g2.x, hC);
            hC = fmaf(__shfl_sync(0xffffffffu, s, 9), g2.y, hC);
            hC = fmaf(__shfl_sync(0xffffffffu, s, 10), g2.z, hC);
            hC = fmaf(__shfl_sync(0xffffffffu, s, 11), g2.w, hC);
            hD = fmaf(__shfl_sync(0xffffffffu, s, 12), g3.x, hD);
            hD = fmaf(__shfl_sync(0xffffffffu, s, 13), g3.y, hD);
            hD = fmaf(__shfl_sync(0xffffffffu, s, 14), g3.z, hD);
            hD = fmaf(__shfl_sync(0xffffffffu, s, 15), g3.w, hD);
            float h = (hA + hB) + (hC + hD);

            tf0 = fmaf(r.x, h, tf0);
            tf1 = fmaf(r.y, h, tf1);
            tf2 = fmaf(r.z, h, tf2);
            tf3 = fmaf(r.w, h, tf3);

            g0 = n0; g1 = n1; g2 = n2; g3 = n3;
            d = dn; r = rn;
        }
    }

    // invariants
    float i0 = tf0;
    float i1 = tf1 * tf1 + tf2 * tf2 + tf3 * tf3;

    // GroupNorm (population variance, two-pass)
    float m0 = warp_sum(i0) * (1.0f / 32.0f);
    float m1 = warp_sum(i1) * (1.0f / 32.0f);
    float d0 = i0 - m0, d1 = i1 - m1;
    float v0 = warp_sum(d0 * d0) * (1.0f / 32.0f);
    float v1 = warp_sum(d1 * d1) * (1.0f / 32.0f);
    float x0 = d0 * rsqrtf(v0 + GN_EPS) * __ldg(gnw + lane) + __ldg(gnb + lane);
    float x1 = d1 * rsqrtf(v1 + GN_EPS) * __ldg(gnw + 32 + lane) + __ldg(gnb + 32 + lane);

    // mixing: mix[oo=lane] = sum_{o,g} xn[g][o] * Mw[(o*2+g)*32 + oo]
    float mixA = 0.f, mixB = 0.f;
#pragma unroll
    for (int o = 0; o < 32; o++) {
        float a0 = __shfl_sync(0xffffffffu, x0, o);
        float a1 = __shfl_sync(0xffffffffu, x1, o);
        mixA = fmaf(a0, __ldg(Mw + (o * 2 + 0) * 32 + lane), mixA);
        mixB = fmaf(a1, __ldg(Mw + (o * 2 + 1) * 32 + lane), mixB);
    }
    float mix = mixA + mixB;

    // self interaction
    float fv = feat[a * 32 + lane];
    float sp = __ldg(selfB + lane);
#pragma unroll
    for (int f = 0; f < 32; f++) {
        float ff = __shfl_sync(0xffffffffu, fv, f);
        sp = fmaf(ff, __ldg(selfW + lane * 32 + f), sp);
    }

    out[a * 32 + lane] = mix + sp;
}

extern "C" void kernel_launch(void* const* d_in, const int* in_sizes, int n_in,
                              void* d_out, int out_size) {
    const float* in_features = (const float*)d_in[0];
    const float* tensor_rhats = (const float*)d_in[1];
    const float* dist_pairs = (const float*)d_in[2];
    const float* int_weights = (const float*)d_in[3];
    const float* selfint_w = (const float*)d_in[4];
    const float* selfint_b = (const float*)d_in[5];
    const float* mixing_weights = (const float*)d_in[6];
    const float* gn_weight = (const float*)d_in[7];
    const float* gn_bias = (const float*)d_in[8];
    const float* sens_mu = (const float*)d_in[9];
    const float* sens_sigma = (const float*)d_in[10];
    const int* pair_first = (const int*)d_in[11];
    const int* pair_second = (const int*)d_in[12];
    float* out = (float*)d_out;

    int n_atoms = in_sizes[0] / 32;
    int n_pairs = in_sizes[2];

    cudaFuncSetAttribute(k1_precompute_G,
                         cudaFuncAttributeMaxDynamicSharedMemorySize, 65536);

    // k0: segment starts
    k0_seg<<<(n_pairs + 256) / 256, 256>>>(pair_first, n_pairs, n_atoms);

    // k1: G precompute
    int k1_blocks = (n_atoms + 31) / 32;
    k1_precompute_G<<<k1_blocks, 256, 65536>>>(in_features, int_weights, n_atoms);

    // k2: fused main kernel
    int k2_blocks = (n_atoms + 7) / 8;
    k2_main<<<k2_blocks, 256>>>(in_features, tensor_rhats, dist_pairs,
                                selfint_w, selfint_b, mixing_weights,
                                gn_weight, gn_bias, sens_mu, sens_sigma,
                                pair_second, out, n_atoms, n_pairs);
}

// round 6
// speedup vs baseline: 1.1537x; 1.0858x over previous
#include <cuda_runtime.h>
#include <cstdint>

// ---------------------------------------------------------------------------
// HOP interaction layer, restructured for latency tolerance:
//   k0 : seg_start[a] from sorted pair_first
//   k1 : G[j,o,d] = sum_f feat[j,f] * W[d,o,f]        (packed f32x2 GEMM)
//   k2a: h[p,o]   = sum_d sense(p,d) * G[j_p,o,d]     (WARP PER PAIR - no
//        loop-carried chains, 80000 warps hide all L2 latency)
//   k2b: tf[a,c,o]= sum_{p in seg(a)} rhat[p,c]*h[p,o] (contiguous h rows,
//        MLP-unrolled) + invariants + GroupNorm + mixing + self
// ---------------------------------------------------------------------------

#define HARD_CUTOFF 6.5f
#define GN_EPS 1e-5f
#define PI_OVER_13 0.2416609733530618f  // 0.5*pi/6.5

typedef unsigned long long ull;

__device__ float g_G[8192 * 512];        // 16 MB, L2-resident
__device__ float g_H[81920 * 32];        // 10 MB, L2-resident
__device__ int g_seg[8192 + 1];

__device__ __forceinline__ ull pack2(float lo, float hi) {
    ull r;
    asm("mov.b64 %0, {%1, %2};" : "=l"(r) : "f"(lo), "f"(hi));
    return r;
}
__device__ __forceinline__ void unpack2(ull v, float& lo, float& hi) {
    asm("mov.b64 {%0, %1}, %2;" : "=f"(lo), "=f"(hi) : "l"(v));
}
__device__ __forceinline__ ull ffma2(ull a, ull b, ull c) {
    ull d;
    asm("fma.rn.f32x2 %0, %1, %2, %3;" : "=l"(d) : "l"(a), "l"(b), "l"(c));
    return d;
}

// ---- k0: segment starts from sorted pair_first --------------------------
__global__ void k0_seg(const int* __restrict__ pf, int n_pairs, int n_atoms) {
    int p = blockIdx.x * blockDim.x + threadIdx.x;
    if (p > n_pairs) return;
    int cur  = (p < n_pairs) ? pf[p] : n_atoms;
    int prev = (p == 0) ? -1 : pf[p - 1];
    if (cur > n_atoms) cur = n_atoms;
    if (prev > n_atoms) prev = n_atoms;
    for (int a = prev + 1; a <= cur; ++a) g_seg[a] = p;
}

// ---- k1: G precompute, packed fp32x2 ------------------------------------
__global__ void k1_precompute_G(const float* __restrict__ feat,
                                const float* __restrict__ W,  // [d][o][f] 16x32x32
                                int n_atoms) {
    extern __shared__ float Ws[];  // [f][d2][o][e]
    for (int i = threadIdx.x; i < 16384; i += blockDim.x) {
        int d = i >> 10;
        int rem = i & 1023;
        int o = rem >> 5;
        int f = rem & 31;
        Ws[f * 512 + (d >> 1) * 64 + o * 2 + (d & 1)] = W[i];
    }
    __syncthreads();
    const ull* S2 = (const ull*)Ws;  // f*256 + q*32 + o  (q = d/2)

    const int lane = threadIdx.x & 31;
    const int warp = threadIdx.x >> 5;
    const int warps_per_blk = blockDim.x >> 5;
    const int nwarps = warps_per_blk * gridDim.x;
    const int gw = blockIdx.x * warps_per_blk + warp;

    for (int a0 = gw * 4; a0 < n_atoms; a0 += nwarps * 4) {
        float fv[4];
#pragma unroll
        for (int k = 0; k < 4; k++)
            fv[k] = (a0 + k < n_atoms) ? feat[(a0 + k) * 32 + lane] : 0.0f;

        ull acc[4][8];
#pragma unroll
        for (int k = 0; k < 4; k++)
#pragma unroll
            for (int q = 0; q < 8; q++) acc[k][q] = pack2(0.f, 0.f);

#pragma unroll
        for (int f = 0; f < 32; f++) {
            ull w[8];
#pragma unroll
            for (int q = 0; q < 8; q++) w[q] = S2[f * 256 + q * 32 + lane];
#pragma unroll
            for (int k = 0; k < 4; k++) {
                float b = __shfl_sync(0xffffffffu, fv[k], f);
                ull b2 = pack2(b, b);
#pragma unroll
                for (int q = 0; q < 8; q++) acc[k][q] = ffma2(b2, w[q], acc[k][q]);
            }
        }

#pragma unroll
        for (int k = 0; k < 4; k++) {
            int a = a0 + k;
            if (a < n_atoms) {
                float4* dst = (float4*)(g_G + (size_t)a * 512 + lane * 16);
#pragma unroll
                for (int v = 0; v < 4; v++) {
                    float x0, x1, x2, x3;
                    unpack2(acc[k][2 * v], x0, x1);
                    unpack2(acc[k][2 * v + 1], x2, x3);
                    dst[v] = make_float4(x0, x1, x2, x3);
                }
            }
        }
    }
}

// ---- k2a: warp per pair -> h[p, o] --------------------------------------
__global__ void k2a_pairs(const float* __restrict__ dist,    // [P]
                          const float* __restrict__ mu,      // [16]
                          const float* __restrict__ sigma,   // [16]
                          const int* __restrict__ ps,        // [P]
                          int n_pairs) {
    const int p = blockIdx.x * (blockDim.x >> 5) + (threadIdx.x >> 5);
    if (p >= n_pairs) return;
    const int lane = threadIdx.x & 31;

    const int j = __ldg(ps + p);
    const float d = __ldg(dist + p);

    // G row loads issue immediately; sensitivity math overlaps their latency
    const float4* Gp = (const float4*)(g_G + (size_t)j * 512 + lane * 16);
    float4 g0 = __ldg(Gp + 0), g1 = __ldg(Gp + 1),
           g2 = __ldg(Gp + 2), g3 = __ldg(Gp + 3);

    const float mu_l = __ldg(mu + (lane & 15));
    const float inv_sg = __fdividef(1.0f, __ldg(sigma + (lane & 15)));
    float invd = __fdividef(1.0f, d);
    float z = (invd - mu_l) * inv_sg;
    float cc = __cosf(PI_OVER_13 * d);
    float cut = (d < HARD_CUTOFF) ? cc * cc : 0.0f;
    float s = __expf(-0.5f * z * z) * cut;   // valid per-lane for d = lane&15

    float hA = 0.f, hB = 0.f, hC = 0.f, hD = 0.f;
    hA = fmaf(__shfl_sync(0xffffffffu, s, 0), g0.x, hA);
    hA = fmaf(__shfl_sync(0xffffffffu, s, 1), g0.y, hA);
    hA = fmaf(__shfl_sync(0xffffffffu, s, 2), g0.z, hA);
    hA = fmaf(__shfl_sync(0xffffffffu, s, 3), g0.w, hA);
    hB = fmaf(__shfl_sync(0xffffffffu, s, 4), g1.x, hB);
    hB = fmaf(__shfl_sync(0xffffffffu, s, 5), g1.y, hB);
    hB = fmaf(__shfl_sync(0xffffffffu, s, 6), g1.z, hB);
    hB = fmaf(__shfl_sync(0xffffffffu, s, 7), g1.w, hB);
    hC = fmaf(__shfl_sync(0xffffffffu, s, 8), g2.x, hC);
    hC = fmaf(__shfl_sync(0xffffffffu, s, 9), g2.y, hC);
    hC = fmaf(__shfl_sync(0xffffffffu, s, 10), g2.z, hC);
    hC = fmaf(__shfl_sync(0xffffffffu, s, 11), g2.w, hC);
    hD = fmaf(__shfl_sync(0xffffffffu, s, 12), g3.x, hD);
    hD = fmaf(__shfl_sync(0xffffffffu, s, 13), g3.y, hD);
    hD = fmaf(__shfl_sync(0xffffffffu, s, 14), g3.z, hD);
    hD = fmaf(__shfl_sync(0xffffffffu, s, 15), g3.w, hD);

    g_H[(size_t)p * 32 + lane] = (hA + hB) + (hC + hD);
}

__device__ __forceinline__ float warp_sum(float v) {
#pragma unroll
    for (int o = 16; o > 0; o >>= 1) v += __shfl_xor_sync(0xffffffffu, v, o);
    return v;
}

// ---- k2b: warp per atom, contiguous h gather + epilogue -----------------
__global__ void k2b_atoms(const float* __restrict__ feat,
                          const float* __restrict__ rhats,   // [P][4]
                          const float* __restrict__ selfW,   // [o][f]
                          const float* __restrict__ selfB,   // [32]
                          const float* __restrict__ Mw,      // [64][32]
                          const float* __restrict__ gnw,     // [64]
                          const float* __restrict__ gnb,     // [64]
                          float* __restrict__ out,           // [N][32]
                          int n_atoms) {
    const int a = blockIdx.x * (blockDim.x >> 5) + (threadIdx.x >> 5);
    if (a >= n_atoms) return;
    const int lane = threadIdx.x & 31;

    const int pstart = g_seg[a];
    const int pend = g_seg[a + 1];

    float tf0 = 0.f, tf1 = 0.f, tf2 = 0.f, tf3 = 0.f;

#pragma unroll 4
    for (int p = pstart; p < pend; ++p) {
        float h = __ldg(g_H + (size_t)p * 32 + lane);
        float4 r = *(const float4*)(rhats + 4 * p);
        tf0 = fmaf(r.x, h, tf0);
        tf1 = fmaf(r.y, h, tf1);
        tf2 = fmaf(r.z, h, tf2);
        tf3 = fmaf(r.w, h, tf3);
    }

    // invariants
    float i0 = tf0;
    float i1 = tf1 * tf1 + tf2 * tf2 + tf3 * tf3;

    // GroupNorm (population variance, two-pass)
    float m0 = warp_sum(i0) * (1.0f / 32.0f);
    float m1 = warp_sum(i1) * (1.0f / 32.0f);
    float d0 = i0 - m0, d1 = i1 - m1;
    float v0 = warp_sum(d0 * d0) * (1.0f / 32.0f);
    float v1 = warp_sum(d1 * d1) * (1.0f / 32.0f);
    float x0 = d0 * rsqrtf(v0 + GN_EPS) * __ldg(gnw + lane) + __ldg(gnb + lane);
    float x1 = d1 * rsqrtf(v1 + GN_EPS) * __ldg(gnw + 32 + lane) + __ldg(gnb + 32 + lane);

    // mixing
    float mixA = 0.f, mixB = 0.f;
#pragma unroll
    for (int o = 0; o < 32; o++) {
        float a0 = __shfl_sync(0xffffffffu, x0, o);
        float a1 = __shfl_sync(0xffffffffu, x1, o);
        mixA = fmaf(a0, __ldg(Mw + (o * 2 + 0) * 32 + lane), mixA);
        mixB = fmaf(a1, __ldg(Mw + (o * 2 + 1) * 32 + lane), mixB);
    }
    float mix = mixA + mixB;

    // self interaction
    float fv = feat[a * 32 + lane];
    float sp = __ldg(selfB + lane);
#pragma unroll
    for (int f = 0; f < 32; f++) {
        float ff = __shfl_sync(0xffffffffu, fv, f);
        sp = fmaf(ff, __ldg(selfW + lane * 32 + f), sp);
    }

    out[a * 32 + lane] = mix + sp;
}

extern "C" void kernel_launch(void* const* d_in, const int* in_sizes, int n_in,
                              void* d_out, int out_size) {
    const float* in_features = (const float*)d_in[0];
    const float* tensor_rhats = (const float*)d_in[1];
    const float* dist_pairs = (const float*)d_in[2];
    const float* int_weights = (const float*)d_in[3];
    const float* selfint_w = (const float*)d_in[4];
    const float* selfint_b = (const float*)d_in[5];
    const float* mixing_weights = (const float*)d_in[6];
    const float* gn_weight = (const float*)d_in[7];
    const float* gn_bias = (const float*)d_in[8];
    const float* sens_mu = (const float*)d_in[9];
    const float* sens_sigma = (const float*)d_in[10];
    const int* pair_first = (const int*)d_in[11];
    const int* pair_second = (const int*)d_in[12];
    float* out = (float*)d_out;

    int n_atoms = in_sizes[0] / 32;
    int n_pairs = in_sizes[2];

    cudaFuncSetAttribute(k1_precompute_G,
                         cudaFuncAttributeMaxDynamicSharedMemorySize, 65536);

    // k0: segment starts
    k0_seg<<<(n_pairs + 256) / 256, 256>>>(pair_first, n_pairs, n_atoms);

    // k1: G precompute
    int k1_blocks = (n_atoms + 31) / 32;
    k1_precompute_G<<<k1_blocks, 256, 65536>>>(in_features, int_weights, n_atoms);

    // k2a: warp per pair -> h
    int k2a_blocks = (n_pairs + 7) / 8;
    k2a_pairs<<<k2a_blocks, 256>>>(dist_pairs, sens_mu, sens_sigma,
                                   pair_second, n_pairs);

    // k2b: warp per atom -> out
    int k2b_blocks = (n_atoms + 7) / 8;
    k2b_atoms<<<k2b_blocks, 256>>>(in_features, tensor_rhats,
                                   selfint_w, selfint_b, mixing_weights,
                                   gn_weight, gn_bias, out, n_atoms);
}

// round 11
// speedup vs baseline: 1.6098x; 1.3954x over previous
#include <cuda_runtime.h>
#include <cstdint>

// ---------------------------------------------------------------------------
// HOP interaction layer:
//   k0 : seg_start[a] from sorted pair_first
//   k1 : G[j,o,d] = sum_f feat[j,f] * W[d,o,f]   (packed f32x2 GEMM)
//        + self[a,o] = feat[a] @ selfW^T + b     (transposed smem, no
//          divergent loads — this was 35us of L1 replay in k2b)
//   k2a: h[p,o]   = sum_d sense(p,d) * G[j_p,o,d]   (warp per pair)
//   k2b: tf[a,c,o]= sum_p rhat[p,c]*h[p,o] + invariants + GN + mixing + self
// ---------------------------------------------------------------------------

#define HARD_CUTOFF 6.5f
#define GN_EPS 1e-5f
#define PI_OVER_13 0.2416609733530618f  // 0.5*pi/6.5

typedef unsigned long long ull;

__device__ float g_G[8192 * 512];        // 16 MB, L2-resident
__device__ float g_H[81920 * 32];        // 10 MB, L2-resident
__device__ float g_self[8192 * 32];      // 1 MB
__device__ int g_seg[8192 + 1];

__device__ __forceinline__ ull pack2(float lo, float hi) {
    ull r;
    asm("mov.b64 %0, {%1, %2};" : "=l"(r) : "f"(lo), "f"(hi));
    return r;
}
__device__ __forceinline__ void unpack2(ull v, float& lo, float& hi) {
    asm("mov.b64 {%0, %1}, %2;" : "=f"(lo), "=f"(hi) : "l"(v));
}
__device__ __forceinline__ ull ffma2(ull a, ull b, ull c) {
    ull d;
    asm("fma.rn.f32x2 %0, %1, %2, %3;" : "=l"(d) : "l"(a), "l"(b), "l"(c));
    return d;
}

// ---- k0: segment starts from sorted pair_first --------------------------
__global__ void k0_seg(const int* __restrict__ pf, int n_pairs, int n_atoms) {
    int p = blockIdx.x * blockDim.x + threadIdx.x;
    if (p > n_pairs) return;
    int cur  = (p < n_pairs) ? pf[p] : n_atoms;
    int prev = (p == 0) ? -1 : pf[p - 1];
    if (cur > n_atoms) cur = n_atoms;
    if (prev > n_atoms) prev = n_atoms;
    for (int a = prev + 1; a <= cur; ++a) g_seg[a] = p;
}

// ---- k1: G precompute + self interaction --------------------------------
// dynamic smem: [0, 16384) = W transposed packed, [16384, 17408) = selfW^T,
//               [17408, 17440) = selfB
__global__ void k1_precompute_G(const float* __restrict__ feat,
                                const float* __restrict__ W,     // [d][o][f]
                                const float* __restrict__ selfW, // [o][f]
                                const float* __restrict__ selfB, // [32]
                                int n_atoms) {
    extern __shared__ float Ws[];
    float* sWt = Ws + 16384;   // [f][o] transposed
    float* sB  = Ws + 16384 + 1024;
    for (int i = threadIdx.x; i < 16384; i += blockDim.x) {
        int d = i >> 10;
        int rem = i & 1023;
        int o = rem >> 5;
        int f = rem & 31;
        Ws[f * 512 + (d >> 1) * 64 + o * 2 + (d & 1)] = W[i];
    }
    for (int i = threadIdx.x; i < 1024; i += blockDim.x)
        sWt[(i & 31) * 32 + (i >> 5)] = selfW[i];   // sWt[f][o] = selfW[o][f]
    if (threadIdx.x < 32) sB[threadIdx.x] = selfB[threadIdx.x];
    __syncthreads();
    const ull* S2 = (const ull*)Ws;  // f*256 + q*32 + o  (q = d/2)

    const int lane = threadIdx.x & 31;
    const int warp = threadIdx.x >> 5;
    const int warps_per_blk = blockDim.x >> 5;
    const int nwarps = warps_per_blk * gridDim.x;
    const int gw = blockIdx.x * warps_per_blk + warp;

    for (int a0 = gw * 4; a0 < n_atoms; a0 += nwarps * 4) {
        float fv[4];
#pragma unroll
        for (int k = 0; k < 4; k++)
            fv[k] = (a0 + k < n_atoms) ? feat[(a0 + k) * 32 + lane] : 0.0f;

        ull acc[4][8];
        float sp[4];
#pragma unroll
        for (int k = 0; k < 4; k++) {
            sp[k] = sB[lane];
#pragma unroll
            for (int q = 0; q < 8; q++) acc[k][q] = pack2(0.f, 0.f);
        }

#pragma unroll
        for (int f = 0; f < 32; f++) {
            ull w[8];
#pragma unroll
            for (int q = 0; q < 8; q++) w[q] = S2[f * 256 + q * 32 + lane];
            float swt = sWt[f * 32 + lane];
#pragma unroll
            for (int k = 0; k < 4; k++) {
                float b = __shfl_sync(0xffffffffu, fv[k], f);
                ull b2 = pack2(b, b);
#pragma unroll
                for (int q = 0; q < 8; q++) acc[k][q] = ffma2(b2, w[q], acc[k][q]);
                sp[k] = fmaf(b, swt, sp[k]);
            }
        }

#pragma unroll
        for (int k = 0; k < 4; k++) {
            int a = a0 + k;
            if (a < n_atoms) {
                float4* dst = (float4*)(g_G + (size_t)a * 512 + lane * 16);
#pragma unroll
                for (int v = 0; v < 4; v++) {
                    float x0, x1, x2, x3;
                    unpack2(acc[k][2 * v], x0, x1);
                    unpack2(acc[k][2 * v + 1], x2, x3);
                    dst[v] = make_float4(x0, x1, x2, x3);
                }
                g_self[a * 32 + lane] = sp[k];
            }
        }
    }
}

// ---- k2a: warp per pair -> h[p, o] --------------------------------------
__global__ void k2a_pairs(const float* __restrict__ dist,    // [P]
                          const float* __restrict__ mu,      // [16]
                          const float* __restrict__ sigma,   // [16]
                          const int* __restrict__ ps,        // [P]
                          int n_pairs) {
    const int p = blockIdx.x * (blockDim.x >> 5) + (threadIdx.x >> 5);
    if (p >= n_pairs) return;
    const int lane = threadIdx.x & 31;

    const int j = __ldg(ps + p);
    const float d = __ldg(dist + p);

    const float4* Gp = (const float4*)(g_G + (size_t)j * 512 + lane * 16);
    float4 g0 = __ldg(Gp + 0), g1 = __ldg(Gp + 1),
           g2 = __ldg(Gp + 2), g3 = __ldg(Gp + 3);

    const float mu_l = __ldg(mu + (lane & 15));
    const float inv_sg = __fdividef(1.0f, __ldg(sigma + (lane & 15)));
    float invd = __fdividef(1.0f, d);
    float z = (invd - mu_l) * inv_sg;
    float cc = __cosf(PI_OVER_13 * d);
    float cut = (d < HARD_CUTOFF) ? cc * cc : 0.0f;
    float s = __expf(-0.5f * z * z) * cut;

    float hA = 0.f, hB = 0.f, hC = 0.f, hD = 0.f;
    hA = fmaf(__shfl_sync(0xffffffffu, s, 0), g0.x, hA);
    hA = fmaf(__shfl_sync(0xffffffffu, s, 1), g0.y, hA);
    hA = fmaf(__shfl_sync(0xffffffffu, s, 2), g0.z, hA);
    hA = fmaf(__shfl_sync(0xffffffffu, s, 3), g0.w, hA);
    hB = fmaf(__shfl_sync(0xffffffffu, s, 4), g1.x, hB);
    hB = fmaf(__shfl_sync(0xffffffffu, s, 5), g1.y, hB);
    hB = fmaf(__shfl_sync(0xffffffffu, s, 6), g1.z, hB);
    hB = fmaf(__shfl_sync(0xffffffffu, s, 7), g1.w, hB);
    hC = fmaf(__shfl_sync(0xffffffffu, s, 8), g2.x, hC);
    hC = fmaf(__shfl_sync(0xffffffffu, s, 9), g2.y, hC);
    hC = fmaf(__shfl_sync(0xffffffffu, s, 10), g2.z, hC);
    hC = fmaf(__shfl_sync(0xffffffffu, s, 11), g2.w, hC);
    hD = fmaf(__shfl_sync(0xffffffffu, s, 12), g3.x, hD);
    hD = fmaf(__shfl_sync(0xffffffffu, s, 13), g3.y, hD);
    hD = fmaf(__shfl_sync(0xffffffffu, s, 14), g3.z, hD);
    hD = fmaf(__shfl_sync(0xffffffffu, s, 15), g3.w, hD);

    g_H[(size_t)p * 32 + lane] = (hA + hB) + (hC + hD);
}

__device__ __forceinline__ float warp_sum(float v) {
#pragma unroll
    for (int o = 16; o > 0; o >>= 1) v += __shfl_xor_sync(0xffffffffu, v, o);
    return v;
}

// ---- k2b: warp per atom, contiguous h gather + epilogue -----------------
__global__ void k2b_atoms(const float* __restrict__ rhats,   // [P][4]
                          const float* __restrict__ Mw,      // [64][32]
                          const float* __restrict__ gnw,     // [64]
                          const float* __restrict__ gnb,     // [64]
                          float* __restrict__ out,           // [N][32]
                          int n_atoms) {
    const int a = blockIdx.x * (blockDim.x >> 5) + (threadIdx.x >> 5);
    if (a >= n_atoms) return;
    const int lane = threadIdx.x & 31;

    const int pstart = g_seg[a];
    const int pend = g_seg[a + 1];

    float tf0 = 0.f, tf1 = 0.f, tf2 = 0.f, tf3 = 0.f;

#pragma unroll 4
    for (int p = pstart; p < pend; ++p) {
        float h = __ldg(g_H + (size_t)p * 32 + lane);
        float4 r = *(const float4*)(rhats + 4 * p);
        tf0 = fmaf(r.x, h, tf0);
        tf1 = fmaf(r.y, h, tf1);
        tf2 = fmaf(r.z, h, tf2);
        tf3 = fmaf(r.w, h, tf3);
    }

    // invariants
    float i0 = tf0;
    float i1 = tf1 * tf1 + tf2 * tf2 + tf3 * tf3;

    // GroupNorm (population variance, two-pass)
    float m0 = warp_sum(i0) * (1.0f / 32.0f);
    float m1 = warp_sum(i1) * (1.0f / 32.0f);
    float d0 = i0 - m0, d1 = i1 - m1;
    float v0 = warp_sum(d0 * d0) * (1.0f / 32.0f);
    float v1 = warp_sum(d1 * d1) * (1.0f / 32.0f);
    float x0 = d0 * rsqrtf(v0 + GN_EPS) * __ldg(gnw + lane) + __ldg(gnb + lane);
    float x1 = d1 * rsqrtf(v1 + GN_EPS) * __ldg(gnw + 32 + lane) + __ldg(gnb + 32 + lane);

    // mixing (Mw rows are coalesced 128B loads, L1-resident after warm-up)
    float mixA = 0.f, mixB = 0.f;
#pragma unroll
    for (int o = 0; o < 32; o++) {
        float a0 = __shfl_sync(0xffffffffu, x0, o);
        float a1 = __shfl_sync(0xffffffffu, x1, o);
        mixA = fmaf(a0, __ldg(Mw + (o * 2 + 0) * 32 + lane), mixA);
        mixB = fmaf(a1, __ldg(Mw + (o * 2 + 1) * 32 + lane), mixB);
    }

    out[a * 32 + lane] = (mixA + mixB) + g_self[a * 32 + lane];
}

extern "C" void kernel_launch(void* const* d_in, const int* in_sizes, int n_in,
                              void* d_out, int out_size) {
    const float* in_features = (const float*)d_in[0];
    const float* tensor_rhats = (const float*)d_in[1];
    const float* dist_pairs = (const float*)d_in[2];
    const float* int_weights = (const float*)d_in[3];
    const float* selfint_w = (const float*)d_in[4];
    const float* selfint_b = (const float*)d_in[5];
    const float* mixing_weights = (const float*)d_in[6];
    const float* gn_weight = (const float*)d_in[7];
    const float* gn_bias = (const float*)d_in[8];
    const float* sens_mu = (const float*)d_in[9];
    const float* sens_sigma = (const float*)d_in[10];
    const int* pair_first = (const int*)d_in[11];
    const int* pair_second = (const int*)d_in[12];
    float* out = (float*)d_out;

    int n_atoms = in_sizes[0] / 32;
    int n_pairs = in_sizes[2];

    cudaFuncSetAttribute(k1_precompute_G,
                         cudaFuncAttributeMaxDynamicSharedMemorySize, 70912);

    // k0: segment starts
    k0_seg<<<(n_pairs + 256) / 256, 256>>>(pair_first, n_pairs, n_atoms);

    // k1: G + self precompute
    int k1_blocks = (n_atoms + 31) / 32;
    k1_precompute_G<<<k1_blocks, 256, 70912>>>(in_features, int_weights,
                                               selfint_w, selfint_b, n_atoms);

    // k2a: warp per pair -> h
    int k2a_blocks = (n_pairs + 7) / 8;
    k2a_pairs<<<k2a_blocks, 256>>>(dist_pairs, sens_mu, sens_sigma,
                                   pair_second, n_pairs);

    // k2b: warp per atom -> out
    int k2b_blocks = (n_atoms + 7) / 8;
    k2b_atoms<<<k2b_blocks, 256>>>(tensor_rhats, mixing_weights,
                                   gn_weight, gn_bias, out, n_atoms);
}

// round 12
// speedup vs baseline: 2.0665x; 1.2837x over previous
#include <cuda_runtime.h>
#include <cuda_fp16.h>
#include <cstdint>

// ---------------------------------------------------------------------------
// HOP interaction layer:
//   k1 : [gemm blocks] G[j,o,d] (fp16) = sum_f feat[j,f]*W[d,o,f]  (f32x2 GEMM)
//        + self[a,o] = feat[a] @ selfW^T + b
//        [seg blocks] seg_start[a] from sorted pair_first (fused, saves launch)
//   k2a: h[p,o] = sum_d sense(p,d) * G[j_p,o,d]   (warp per pair, fp16 G rows
//        = 1KB -> halves the 160MB L2 traffic that dominated)
//   k2b: tf[a,c,o]= sum_p rhat[p,c]*h[p,o] + invariants + GN + mixing + self
// ---------------------------------------------------------------------------

#define HARD_CUTOFF 6.5f
#define GN_EPS 1e-5f
#define PI_OVER_13 0.2416609733530618f  // 0.5*pi/6.5

typedef unsigned long long ull;

__device__ __half g_Gh[8192 * 512];      // 8 MB, L2-resident  [atom][o][d]
__device__ float g_H[81920 * 32];        // 10 MB, L2-resident
__device__ float g_self[8192 * 32];      // 1 MB
__device__ int g_seg[8192 + 1];

__device__ __forceinline__ ull pack2(float lo, float hi) {
    ull r;
    asm("mov.b64 %0, {%1, %2};" : "=l"(r) : "f"(lo), "f"(hi));
    return r;
}
__device__ __forceinline__ void unpack2(ull v, float& lo, float& hi) {
    asm("mov.b64 {%0, %1}, %2;" : "=f"(lo), "=f"(hi) : "l"(v));
}
__device__ __forceinline__ ull ffma2(ull a, ull b, ull c) {
    ull d;
    asm("fma.rn.f32x2 %0, %1, %2, %3;" : "=l"(d) : "l"(a), "l"(b), "l"(c));
    return d;
}

// ---- k1: G (fp16) + self precompute, with fused seg-table blocks --------
// dynamic smem: [0,16384) W packed; [16384,17408) selfW^T; [17408,17440) selfB
__global__ void k1_precompute_G(const float* __restrict__ feat,
                                const float* __restrict__ W,     // [d][o][f]
                                const float* __restrict__ selfW, // [o][f]
                                const float* __restrict__ selfB, // [32]
                                const int* __restrict__ pf,      // [P] sorted
                                int n_atoms, int n_pairs, int gemm_blocks) {
    if ((int)blockIdx.x >= gemm_blocks) {
        // ---- seg-table role (entire block takes this branch) ----
        int p = (blockIdx.x - gemm_blocks) * blockDim.x + threadIdx.x;
        if (p > n_pairs) return;
        int cur  = (p < n_pairs) ? pf[p] : n_atoms;
        int prev = (p == 0) ? -1 : pf[p - 1];
        if (cur > n_atoms) cur = n_atoms;
        if (prev > n_atoms) prev = n_atoms;
        for (int a = prev + 1; a <= cur; ++a) g_seg[a] = p;
        return;
    }

    extern __shared__ float Ws[];
    float* sWt = Ws + 16384;   // [f][o]
    float* sB  = Ws + 16384 + 1024;
    for (int i = threadIdx.x; i < 16384; i += blockDim.x) {
        int d = i >> 10;
        int rem = i & 1023;
        int o = rem >> 5;
        int f = rem & 31;
        Ws[f * 512 + (d >> 1) * 64 + o * 2 + (d & 1)] = W[i];
    }
    for (int i = threadIdx.x; i < 1024; i += blockDim.x)
        sWt[(i & 31) * 32 + (i >> 5)] = selfW[i];
    if (threadIdx.x < 32) sB[threadIdx.x] = selfB[threadIdx.x];
    __syncthreads();
    const ull* S2 = (const ull*)Ws;  // f*256 + q*32 + o  (q = d/2)

    const int lane = threadIdx.x & 31;
    const int warp = threadIdx.x >> 5;
    const int warps_per_blk = blockDim.x >> 5;
    const int nwarps = warps_per_blk * gemm_blocks;
    const int gw = blockIdx.x * warps_per_blk + warp;

    for (int a0 = gw * 4; a0 < n_atoms; a0 += nwarps * 4) {
        float fv[4];
#pragma unroll
        for (int k = 0; k < 4; k++)
            fv[k] = (a0 + k < n_atoms) ? feat[(a0 + k) * 32 + lane] : 0.0f;

        ull acc[4][8];
        float sp[4];
#pragma unroll
        for (int k = 0; k < 4; k++) {
            sp[k] = sB[lane];
#pragma unroll
            for (int q = 0; q < 8; q++) acc[k][q] = pack2(0.f, 0.f);
        }

#pragma unroll
        for (int f = 0; f < 32; f++) {
            ull w[8];
#pragma unroll
            for (int q = 0; q < 8; q++) w[q] = S2[f * 256 + q * 32 + lane];
            float swt = sWt[f * 32 + lane];
#pragma unroll
            for (int k = 0; k < 4; k++) {
                float b = __shfl_sync(0xffffffffu, fv[k], f);
                ull b2 = pack2(b, b);
#pragma unroll
                for (int q = 0; q < 8; q++) acc[k][q] = ffma2(b2, w[q], acc[k][q]);
                sp[k] = fmaf(b, swt, sp[k]);
            }
        }

#pragma unroll
        for (int k = 0; k < 4; k++) {
            int a = a0 + k;
            if (a < n_atoms) {
                // pack 16 fp32 -> 16 fp16 (8 half2) = 32B = one uint4 x2
                uint4 u[2];
                unsigned* uu = (unsigned*)u;
#pragma unroll
                for (int q = 0; q < 8; q++) {
                    float x0, x1;
                    unpack2(acc[k][q], x0, x1);
                    __half2 h2 = __floats2half2_rn(x0, x1);
                    uu[q] = *(unsigned*)&h2;
                }
                uint4* dst = (uint4*)(g_Gh + (size_t)a * 512 + lane * 16);
                dst[0] = u[0];
                dst[1] = u[1];
                g_self[a * 32 + lane] = sp[k];
            }
        }
    }
}

// ---- k2a: warp per pair -> h[p, o], fp16 G ------------------------------
__global__ void k2a_pairs(const float* __restrict__ dist,    // [P]
                          const float* __restrict__ mu,      // [16]
                          const float* __restrict__ sigma,   // [16]
                          const int* __restrict__ ps,        // [P]
                          int n_pairs) {
    const int p = blockIdx.x * (blockDim.x >> 5) + (threadIdx.x >> 5);
    if (p >= n_pairs) return;
    const int lane = threadIdx.x & 31;

    const int j = __ldg(ps + p);
    const float d = __ldg(dist + p);

    // 2x LDG.128 = 16 fp16 G values for this (o=lane) row
    const uint4* Gp = (const uint4*)(g_Gh + (size_t)j * 512 + lane * 16);
    uint4 u0 = __ldg(Gp + 0), u1 = __ldg(Gp + 1);

    const float mu_l = __ldg(mu + (lane & 15));
    const float inv_sg = __fdividef(1.0f, __ldg(sigma + (lane & 15)));
    float invd = __fdividef(1.0f, d);
    float z = (invd - mu_l) * inv_sg;
    float cc = __cosf(PI_OVER_13 * d);
    float cut = (d < HARD_CUTOFF) ? cc * cc : 0.0f;
    float s = __expf(-0.5f * z * z) * cut;   // per-lane, d = lane&15

    const unsigned* uu = (const unsigned*)&u0;  // u0,u1 contiguous? not guaranteed
    unsigned ua[8] = {u0.x, u0.y, u0.z, u0.w, u1.x, u1.y, u1.z, u1.w};

    float hA = 0.f, hB = 0.f, hC = 0.f, hD = 0.f;
#pragma unroll
    for (int q = 0; q < 8; q++) {
        __half2 h2 = *(__half2*)&ua[q];
        float2 g2 = __half22float2(h2);
        float s0 = __shfl_sync(0xffffffffu, s, 2 * q);
        float s1 = __shfl_sync(0xffffffffu, s, 2 * q + 1);
        if (q < 2)      { hA = fmaf(s0, g2.x, hA); hA = fmaf(s1, g2.y, hA); }
        else if (q < 4) { hB = fmaf(s0, g2.x, hB); hB = fmaf(s1, g2.y, hB); }
        else if (q < 6) { hC = fmaf(s0, g2.x, hC); hC = fmaf(s1, g2.y, hC); }
        else            { hD = fmaf(s0, g2.x, hD); hD = fmaf(s1, g2.y, hD); }
    }
    (void)uu;

    g_H[(size_t)p * 32 + lane] = (hA + hB) + (hC + hD);
}

__device__ __forceinline__ float warp_sum(float v) {
#pragma unroll
    for (int o = 16; o > 0; o >>= 1) v += __shfl_xor_sync(0xffffffffu, v, o);
    return v;
}

// ---- k2b: warp per atom, contiguous h gather + epilogue -----------------
__global__ void k2b_atoms(const float* __restrict__ rhats,   // [P][4]
                          const float* __restrict__ Mw,      // [64][32]
                          const float* __restrict__ gnw,     // [64]
                          const float* __restrict__ gnb,     // [64]
                          float* __restrict__ out,           // [N][32]
                          int n_atoms) {
    const int a = blockIdx.x * (blockDim.x >> 5) + (threadIdx.x >> 5);
    if (a >= n_atoms) return;
    const int lane = threadIdx.x & 31;

    const int pstart = g_seg[a];
    const int pend = g_seg[a + 1];

    float tf0 = 0.f, tf1 = 0.f, tf2 = 0.f, tf3 = 0.f;

#pragma unroll 4
    for (int p = pstart; p < pend; ++p) {
        float h = __ldg(g_H + (size_t)p * 32 + lane);
        float4 r = *(const float4*)(rhats + 4 * p);
        tf0 = fmaf(r.x, h, tf0);
        tf1 = fmaf(r.y, h, tf1);
        tf2 = fmaf(r.z, h, tf2);
        tf3 = fmaf(r.w, h, tf3);
    }

    float i0 = tf0;
    float i1 = tf1 * tf1 + tf2 * tf2 + tf3 * tf3;

    float m0 = warp_sum(i0) * (1.0f / 32.0f);
    float m1 = warp_sum(i1) * (1.0f / 32.0f);
    float d0 = i0 - m0, d1 = i1 - m1;
    float v0 = warp_sum(d0 * d0) * (1.0f / 32.0f);
    float v1 = warp_sum(d1 * d1) * (1.0f / 32.0f);
    float x0 = d0 * rsqrtf(v0 + GN_EPS) * __ldg(gnw + lane) + __ldg(gnb + lane);
    float x1 = d1 * rsqrtf(v1 + GN_EPS) * __ldg(gnw + 32 + lane) + __ldg(gnb + 32 + lane);

    float mixA = 0.f, mixB = 0.f;
#pragma unroll
    for (int o = 0; o < 32; o++) {
        float a0 = __shfl_sync(0xffffffffu, x0, o);
        float a1 = __shfl_sync(0xffffffffu, x1, o);
        mixA = fmaf(a0, __ldg(Mw + (o * 2 + 0) * 32 + lane), mixA);
        mixB = fmaf(a1, __ldg(Mw + (o * 2 + 1) * 32 + lane), mixB);
    }

    out[a * 32 + lane] = (mixA + mixB) + g_self[a * 32 + lane];
}

extern "C" void kernel_launch(void* const* d_in, const int* in_sizes, int n_in,
                              void* d_out, int out_size) {
    const float* in_features = (const float*)d_in[0];
    const float* tensor_rhats = (const float*)d_in[1];
    const float* dist_pairs = (const float*)d_in[2];
    const float* int_weights = (const float*)d_in[3];
    const float* selfint_w = (const float*)d_in[4];
    const float* selfint_b = (const float*)d_in[5];
    const float* mixing_weights = (const float*)d_in[6];
    const float* gn_weight = (const float*)d_in[7];
    const float* gn_bias = (const float*)d_in[8];
    const float* sens_mu = (const float*)d_in[9];
    const float* sens_sigma = (const float*)d_in[10];
    const int* pair_first = (const int*)d_in[11];
    const int* pair_second = (const int*)d_in[12];
    float* out = (float*)d_out;

    int n_atoms = in_sizes[0] / 32;
    int n_pairs = in_sizes[2];

    cudaFuncSetAttribute(k1_precompute_G,
                         cudaFuncAttributeMaxDynamicSharedMemorySize, 70912);

    // k1: G + self precompute (gemm blocks) + seg table (extra blocks)
    int gemm_blocks = (n_atoms + 31) / 32;
    int seg_blocks = (n_pairs + 256) / 256;
    k1_precompute_G<<<gemm_blocks + seg_blocks, 256, 70912>>>(
        in_features, int_weights, selfint_w, selfint_b, pair_first,
        n_atoms, n_pairs, gemm_blocks);

    // k2a: warp per pair -> h
    int k2a_blocks = (n_pairs + 7) / 8;
    k2a_pairs<<<k2a_blocks, 256>>>(dist_pairs, sens_mu, sens_sigma,
                                   pair_second, n_pairs);

    // k2b: warp per atom -> out
    int k2b_blocks = (n_atoms + 7) / 8;
    k2b_atoms<<<k2b_blocks, 256>>>(tensor_rhats, mixing_weights,
                                   gn_weight, gn_bias, out, n_atoms);
}